// round 14
// baseline (speedup 1.0000x reference)
#include <cuda_runtime.h>
#include <math.h>

#define NBLK  148
#define WPB   16
#define TW    (NBLK * WPB)     // 2368 warps
#define CROWS 64               // rows per warp-chunk (8 octets)
#define DOUT  64

// Per-chunk published data (indexed -> deterministic) + per-batch counters.
__device__ float2 g_part[8192];
__device__ float2 g_head[8192];
__device__ float2 g_tail[8192];
__device__ int    g_cnt[128];  // zero-init; self-resetting

__global__ __launch_bounds__(512, 1)
void k_all(const float* __restrict__ x,
           const float* __restrict__ w1,
           const float* __restrict__ b1,
           const float* __restrict__ w2,
           const float* __restrict__ b2,
           const float* __restrict__ w3,
           const float* __restrict__ b3,
           float* __restrict__ out,
           int rows, int S)
{
    const int tid  = threadIdx.x;
    const int lane = tid & 31;
    const int q    = lane & 3;            // column slice within quad
    const int sub  = lane >> 2;           // row within octet (0..7)
    const int w    = tid >> 5;            // warp in block
    const int bid  = blockIdx.x;

    const int nchunks = rows / CROWS;     // 8192
    const int cpb     = S / CROWS;        // 64 chunks per batch

    const float4* __restrict__ X = reinterpret_cast<const float4*>(x);
    const float4* __restrict__ W = reinterpret_cast<const float4*>(w1);

    // proven quad-map weight layout
    float4 wa0[8], wa1[8];
    #pragma unroll
    for (int k = 0; k < 8; ++k) { wa0[k] = W[q + 4*k]; wa1[k] = W[32 + q + 4*k]; }
    const float bb0 = b1[0], bb1 = b1[1];
    const float c0 = w2[0], c1 = w2[1], cb = b2[0];

    // ---- stream: warp-chunks of 64 consecutive rows, t stays in registers ----
    for (int wc = w * NBLK + bid; wc < nchunks; wc += TW) {
        const int r0 = wc * CROWS;
        float fs = 0.f, fss = 0.f;
        float tprev = 0.f, hx = 0.f, hy = 0.f, tx = 0.f, ty = 0.f;

        #pragma unroll
        for (int oc = 0; oc < 8; ++oc) {
            const size_t base = (size_t)(r0 + oc * 8 + sub) * 32 + q;
            float4 v[8];
            #pragma unroll
            for (int k = 0; k < 8; ++k) v[k] = X[base + 4*k];

            float d0 = 0.f, d1 = 0.f;
            #pragma unroll
            for (int k = 0; k < 8; ++k) {
                d0 += v[k].x*wa0[k].x + v[k].y*wa0[k].y + v[k].z*wa0[k].z + v[k].w*wa0[k].w;
                d1 += v[k].x*wa1[k].x + v[k].y*wa1[k].y + v[k].z*wa1[k].z + v[k].w*wa1[k].w;
            }
            d0 += __shfl_xor_sync(0xffffffffu, d0, 1);
            d0 += __shfl_xor_sync(0xffffffffu, d0, 2);
            d1 += __shfl_xor_sync(0xffffffffu, d1, 1);
            d1 += __shfl_xor_sync(0xffffffffu, d1, 2);

            const float h0 = fmaxf(d0 + bb0, 0.0f);
            const float h1 = fmaxf(d1 + bb1, 0.0f);
            const float t  = fmaf(c1, h1, fmaf(c0, h0, cb));  // all lanes

            // inter-octet diffs: prev octet rows 6,7 vs this octet rows 0,1
            const float thead = __shfl_up_sync(0xffffffffu, t, 24);
            if (oc > 0 && q == 0 && sub >= 6) {
                const float l = logf(fabsf(thead - tprev) + 1e-6f);
                fs += l; fss = fmaf(l, l, fss);
            }
            // in-octet diffs: rows sub<6 vs sub+2 (lane+8)
            const float t2 = __shfl_down_sync(0xffffffffu, t, 8);
            if (q == 0 && sub < 6) {
                const float l = logf(fabsf(t2 - t) + 1e-6f);
                fs += l; fss = fmaf(l, l, fss);
            }
            if (oc == 0) {
                hx = __shfl_sync(0xffffffffu, t, 0);   // t[r0]
                hy = __shfl_sync(0xffffffffu, t, 4);   // t[r0+1]
            }
            if (oc == 7) {
                tx = __shfl_sync(0xffffffffu, t, 24);  // t[r0+62]
                ty = __shfl_sync(0xffffffffu, t, 28);  // t[r0+63]
            }
            tprev = t;
        }

        // warp-reduce chunk partials; lane 0 publishes (plain STG, no fence)
        #pragma unroll
        for (int off = 16; off; off >>= 1) {
            fs  += __shfl_xor_sync(0xffffffffu, fs,  off);
            fss += __shfl_xor_sync(0xffffffffu, fss, off);
        }
        if (lane == 0) {
            g_part[wc] = make_float2(fs, fss);
            g_head[wc] = make_float2(hx, hy);
            g_tail[wc] = make_float2(tx, ty);
        }
    }

    // ---- block-end publish: one fence, then counter atomics by tid 0 ----
    __threadfence();
    __syncthreads();

    __shared__ int fin[64];
    __shared__ int nfin;
    if (tid == 0) {
        int n = 0;
        for (int w2 = 0; w2 < WPB; ++w2)
            for (int wc = w2 * NBLK + bid; wc < nchunks; wc += TW) {
                const int b = wc / cpb;
                if (atomicAdd(&g_cnt[b], 1) == cpb - 1) fin[n++] = b;
            }
        nfin = n;
        __threadfence();     // acquire before the block reads foreign slots
    }
    __syncthreads();

    // ---- finalize each completed batch (usually 0 or 1 per block) ----
    __shared__ double sh_s[WPB], sh_ss[WPB];
    __shared__ alignas(16) float sh_stats[2];
    __shared__ alignas(16) float sh_o[64];

    for (int f = 0; f < nfin; ++f) {
        const int b = fin[f];
        const int base = b * cpb;

        double s = 0.0, ss = 0.0;
        if (tid < cpb) {                              // 64 chunk partials
            float2 p = g_part[base + tid];
            s = (double)p.x; ss = (double)p.y;
        } else if (tid < cpb + 2 * (cpb - 1)) {       // 126 boundary diffs
            const int j = tid - cpb, c = j >> 1, k2 = j & 1;
            const float2 tl = g_tail[base + c];
            const float2 hd = g_head[base + c + 1];
            const float d = k2 ? (hd.y - tl.y) : (hd.x - tl.x);
            const float l = logf(fabsf(d) + 1e-6f);
            s = (double)l; ss = (double)l * (double)l;
        }
        #pragma unroll
        for (int off = 16; off; off >>= 1) {
            s  += __shfl_xor_sync(0xffffffffu, s,  off);
            ss += __shfl_xor_sync(0xffffffffu, ss, off);
        }
        if (lane == 0) { sh_s[w] = s; sh_ss[w] = ss; }
        __syncthreads();
        if (w == 0) {
            double ts  = (lane < WPB) ? sh_s[lane]  : 0.0;
            double tss = (lane < WPB) ? sh_ss[lane] : 0.0;
            #pragma unroll
            for (int off = 8; off; off >>= 1) {
                ts  += __shfl_xor_sync(0xffffffffu, ts,  off);
                tss += __shfl_xor_sync(0xffffffffu, tss, off);
            }
            if (lane == 0) {
                const double Nd = (double)(S - 2);
                double mean = ts / Nd;
                double var  = (tss - ts * ts / Nd) / (Nd - 1.0);
                if (var < 0.0) var = 0.0;
                sh_stats[0] = (float)mean;
                sh_stats[1] = (float)sqrt(var);
            }
        }
        __syncthreads();

        if (tid < DOUT)
            sh_o[tid] = tanhf(sh_stats[0] * w3[2*tid] + sh_stats[1] * w3[2*tid + 1] + b3[tid]);
        __syncthreads();

        float4* __restrict__ ob = reinterpret_cast<float4*>(out + (size_t)b * DOUT * DOUT);
        const float4* __restrict__ so = reinterpret_cast<const float4*>(sh_o);
        for (int k = tid; k < (DOUT * DOUT) >> 2; k += 512)
            ob[k] = so[k & ((DOUT >> 2) - 1)];

        if (tid == 0) g_cnt[b] = 0;          // reset for next graph replay
        __syncthreads();
    }
}

extern "C" void kernel_launch(void* const* d_in, const int* in_sizes, int n_in,
                              void* d_out, int out_size)
{
    const float* x  = (const float*)d_in[0];
    const float* w1 = (const float*)d_in[1];
    const float* b1 = (const float*)d_in[2];
    const float* w2 = (const float*)d_in[3];
    const float* b2 = (const float*)d_in[4];
    const float* w3 = (const float*)d_in[5];
    const float* b3 = (const float*)d_in[6];
    float* out = (float*)d_out;

    const int B    = out_size / (DOUT * DOUT);   // 128
    const int rows = in_sizes[0] / 128;          // B * S
    const int S    = rows / B;                   // 4096

    k_all<<<NBLK, 512>>>(x, w1, b1, w2, b2, w3, b3, out, rows, S);
}

// round 16
// speedup vs baseline: 4.1897x; 4.1897x over previous
#include <cuda_runtime.h>
#include <math.h>
#include <stdint.h>

#define DOUT 64
#define STG  65536                 // 64KB stage = 128 rows
#define RING 3

// dynamic smem layout (bytes)
#define OFF_T      (RING * STG)            // 196608: t_sh (16KB)
#define OFF_W      (OFF_T + 16384)         // 212992: w1 copy (1KB)
#define SMEM_TOTAL (OFF_W + 1024)          // 214016

__device__ __forceinline__ uint32_t smem_u32(const void* p) {
    uint32_t a;
    asm("{ .reg .u64 t; cvta.to.shared.u64 t, %1; cvt.u32.u64 %0, t; }" : "=r"(a) : "l"(p));
    return a;
}
__device__ __forceinline__ void cp16(uint32_t dst, const void* src) {
    asm volatile("cp.async.cg.shared.global [%0], [%1], 16;" :: "r"(dst), "l"(src) : "memory");
}
__device__ __forceinline__ void cp_commit() {
    asm volatile("cp.async.commit_group;" ::: "memory");
}
__device__ __forceinline__ void cp_wait2() {
    asm volatile("cp.async.wait_group 2;" ::: "memory");
}

__global__ __launch_bounds__(512, 1)
void k_all(const float* __restrict__ x,
           const float* __restrict__ w1,
           const float* __restrict__ b1,
           const float* __restrict__ w2,
           const float* __restrict__ b2,
           const float* __restrict__ w3,
           const float* __restrict__ b3,
           float* __restrict__ out,
           int S)
{
    extern __shared__ char smem[];
    const uint32_t sb = smem_u32(smem);
    float* const t_sh = reinterpret_cast<float*>(smem + OFF_T);

    __shared__ double sh_s[16], sh_ss[16];
    __shared__ alignas(16) float sh_stats[2];
    __shared__ alignas(16) float sh_o[64];

    const int b    = blockIdx.x;
    const int tid  = threadIdx.x;
    const int lane = tid & 31;
    const int wid  = tid >> 5;
    const int q    = lane & 3;            // column quarter within quad
    const int r    = lane >> 2;           // row within octet (0..7)

    const char* const xb = reinterpret_cast<const char*>(x) + (size_t)b * S * 512;
    const int NS = (S * 512) / STG;       // 32 stages

    // weights -> smem (64 float4)
    if (tid < 64)
        reinterpret_cast<float4*>(smem + OFF_W)[tid] =
            reinterpret_cast<const float4*>(w1)[tid];

    // ---- prologue: stages 0 and 1 in flight ----
    #pragma unroll
    for (int p = 0; p < 2; ++p) {
        const char* src = xb + (size_t)p * STG + tid * 16;
        const uint32_t dst = sb + p * STG + tid * 16;
        #pragma unroll
        for (int i = 0; i < 8; ++i) cp16(dst + i * 8192, src + i * 8192);
        cp_commit();
    }

    const float4* const W4 = reinterpret_cast<const float4*>(smem + OFF_W);
    const float bb0 = b1[0], bb1 = b1[1];
    const float c0 = w2[0], c1 = w2[1], cb = b2[0];

    // ---- pipelined stream ----
    for (int s = 0; s < NS; ++s) {
        if (s + 2 < NS) {
            const int slot = (s + 2) % RING;
            const char* src = xb + (size_t)(s + 2) * STG + tid * 16;
            const uint32_t dst = sb + slot * STG + tid * 16;
            #pragma unroll
            for (int i = 0; i < 8; ++i) cp16(dst + i * 8192, src + i * 8192);
        }
        cp_commit();                       // one group per iter (maybe empty)
        cp_wait2();                        // stage s landed
        __syncthreads();

        // compute stage s: warp wid owns octet wid (16 octets = 128 rows)
        {
            const float4* XS = reinterpret_cast<const float4*>(smem + (s % RING) * STG);
            const int row_local = wid * 8 + r;

            float d0 = 0.f, d1 = 0.f;
            #pragma unroll
            for (int k = 0; k < 8; ++k) {
                const int f = q + 4 * ((k + r) & 7);     // rotated: conflict-free
                const float4 xv  = XS[row_local * 32 + f];
                const float4 w0v = W4[f];
                const float4 w1v = W4[32 + f];
                d0 += xv.x*w0v.x + xv.y*w0v.y + xv.z*w0v.z + xv.w*w0v.w;
                d1 += xv.x*w1v.x + xv.y*w1v.y + xv.z*w1v.z + xv.w*w1v.w;
            }
            d0 += __shfl_xor_sync(0xffffffffu, d0, 1);
            d0 += __shfl_xor_sync(0xffffffffu, d0, 2);
            d1 += __shfl_xor_sync(0xffffffffu, d1, 1);
            d1 += __shfl_xor_sync(0xffffffffu, d1, 2);

            if (q == 0) {
                const float h0 = fmaxf(d0 + bb0, 0.0f);
                const float h1 = fmaxf(d1 + bb1, 0.0f);
                t_sh[s * 128 + row_local] = fmaf(c1, h1, fmaf(c0, h0, cb));
            }
        }
        __syncthreads();                   // slot (s%RING) safe to refill next iter
    }

    // ---- phase 2: R9-verbatim stats + head + broadcast ----
    const int N = S - 2;
    float fs = 0.f, fss = 0.f;
    for (int i = tid; i < N; i += 512) {
        const float d = fabsf(t_sh[i + 2] - t_sh[i]);
        const float l = logf(d + 1e-6f);
        fs += l;
        fss = fmaf(l, l, fss);
    }
    double s2 = (double)fs, ss2 = (double)fss;
    #pragma unroll
    for (int off = 16; off; off >>= 1) {
        s2  += __shfl_xor_sync(0xffffffffu, s2,  off);
        ss2 += __shfl_xor_sync(0xffffffffu, ss2, off);
    }
    if (lane == 0) { sh_s[wid] = s2; sh_ss[wid] = ss2; }
    __syncthreads();
    if (wid == 0) {
        double ts  = (lane < 16) ? sh_s[lane]  : 0.0;
        double tss = (lane < 16) ? sh_ss[lane] : 0.0;
        #pragma unroll
        for (int off = 8; off; off >>= 1) {
            ts  += __shfl_xor_sync(0xffffffffu, ts,  off);
            tss += __shfl_xor_sync(0xffffffffu, tss, off);
        }
        if (lane == 0) {
            const double Nd = (double)N;
            double mean = ts / Nd;
            double var  = (tss - ts * ts / Nd) / (Nd - 1.0);
            if (var < 0.0) var = 0.0;
            sh_stats[0] = (float)mean;
            sh_stats[1] = (float)sqrt(var);
        }
    }
    __syncthreads();

    if (tid < DOUT)
        sh_o[tid] = tanhf(sh_stats[0] * w3[2*tid] + sh_stats[1] * w3[2*tid + 1] + b3[tid]);
    __syncthreads();

    float4* __restrict__ ob = reinterpret_cast<float4*>(out + (size_t)b * DOUT * DOUT);
    const float4* __restrict__ so = reinterpret_cast<const float4*>(sh_o);
    for (int k = tid; k < (DOUT * DOUT) >> 2; k += 512)
        ob[k] = so[k & ((DOUT >> 2) - 1)];
}

extern "C" void kernel_launch(void* const* d_in, const int* in_sizes, int n_in,
                              void* d_out, int out_size)
{
    const float* x  = (const float*)d_in[0];
    const float* w1 = (const float*)d_in[1];
    const float* b1 = (const float*)d_in[2];
    const float* w2 = (const float*)d_in[3];
    const float* b2 = (const float*)d_in[4];
    const float* w3 = (const float*)d_in[5];
    const float* b3 = (const float*)d_in[6];
    float* out = (float*)d_out;

    const int B    = out_size / (DOUT * DOUT);   // 128
    const int rows = in_sizes[0] / 128;          // B * S
    const int S    = rows / B;                   // 4096

    cudaFuncSetAttribute(k_all, cudaFuncAttributeMaxDynamicSharedMemorySize, SMEM_TOTAL);
    k_all<<<B, 512, SMEM_TOTAL>>>(x, w1, b1, w2, b2, w3, b3, out, S);
}

// round 17
// speedup vs baseline: 4.4965x; 1.0732x over previous
#include <cuda_runtime.h>
#include <math.h>

// Scratch: t[b,s] (B=128, S=4096)
__device__ float g_t[128 * 4096];

// ---------------------------------------------------------------------------
// Kernel 1 (R5-verbatim stream, best measured: 43.2us @ 6.2TB/s, 296 blocks):
// t[b,s] = w2·relu(w1·x + b1) + b2, quad-per-row mapping, grid-stride.
// Ends with griddepcontrol.launch_dependents to let k_stats ramp early (PDL).
// ---------------------------------------------------------------------------
__global__ __launch_bounds__(256, 2)
void k_transform(const float* __restrict__ x,
                 const float* __restrict__ w1,
                 const float* __restrict__ b1,
                 const float* __restrict__ w2,
                 const float* __restrict__ b2,
                 int rows)
{
    const int lane = threadIdx.x & 31;
    const int q    = lane & 3;
    const int sub  = lane >> 2;
    const int gwarp  = blockIdx.x * (blockDim.x >> 5) + (threadIdx.x >> 5);
    const int nwarps = gridDim.x * (blockDim.x >> 5);

    const float4* __restrict__ X = reinterpret_cast<const float4*>(x);
    const float4* __restrict__ W = reinterpret_cast<const float4*>(w1);

    float4 wa0[8], wa1[8];
    #pragma unroll
    for (int k = 0; k < 8; ++k) { wa0[k] = W[q + 4*k]; wa1[k] = W[32 + q + 4*k]; }
    const float bb0 = b1[0], bb1 = b1[1];
    const float c0 = w2[0], c1 = w2[1], cb = b2[0];

    const int octets = rows >> 3;
    for (int o = gwarp; o < octets; o += nwarps) {
        const int row = (o << 3) + sub;
        const size_t base = (size_t)row * 32 + q;

        float4 v[8];
        #pragma unroll
        for (int k = 0; k < 8; ++k) v[k] = X[base + 4*k];

        float d0 = 0.f, d1 = 0.f;
        #pragma unroll
        for (int k = 0; k < 8; ++k) {
            d0 += v[k].x*wa0[k].x + v[k].y*wa0[k].y + v[k].z*wa0[k].z + v[k].w*wa0[k].w;
            d1 += v[k].x*wa1[k].x + v[k].y*wa1[k].y + v[k].z*wa1[k].z + v[k].w*wa1[k].w;
        }
        d0 += __shfl_xor_sync(0xffffffffu, d0, 1);
        d0 += __shfl_xor_sync(0xffffffffu, d0, 2);
        d1 += __shfl_xor_sync(0xffffffffu, d1, 1);
        d1 += __shfl_xor_sync(0xffffffffu, d1, 2);

        if (q == 0) {
            float h0 = fmaxf(d0 + bb0, 0.0f);
            float h1 = fmaxf(d1 + bb1, 0.0f);
            g_t[row] = fmaf(c1, h1, fmaf(c0, h0, cb));
        }
    }

    // PDL: allow the dependent kernel to begin launching/ramping now.
    asm volatile("griddepcontrol.launch_dependents;" ::: "memory");
}

// ---------------------------------------------------------------------------
// Kernel 2 (R5-verbatim epilogue): one 512-thread block per batch.
// griddepcontrol.wait gates the g_t reads on k_transform's full completion;
// everything before it (ramp, const loads) overlaps k_transform's tail.
// ---------------------------------------------------------------------------
__global__ __launch_bounds__(512)
void k_stats(const float* __restrict__ w3,
             const float* __restrict__ b3,
             float* __restrict__ out,
             int S, int dout)
{
    __shared__ alignas(16) float  t_sh[4096 + 4];
    __shared__ double sh_s[16], sh_ss[16];
    __shared__ alignas(16) float sh_stats[2];
    __shared__ alignas(16) float sh_o[64];

    const int b    = blockIdx.x;
    const int tid  = threadIdx.x;
    const int lane = tid & 31;
    const int wid  = tid >> 5;
    const int nthr = blockDim.x;

    // Wait for k_transform's stores to be globally visible (PDL gate).
    asm volatile("griddepcontrol.wait;" ::: "memory");

    // Phase A: coalesced float4 copy of t row into shared
    const float4* __restrict__ T4 = reinterpret_cast<const float4*>(g_t + (size_t)b * S);
    float4* __restrict__ S4 = reinterpret_cast<float4*>(t_sh);
    for (int k = tid; k < (S >> 2); k += nthr) S4[k] = T4[k];
    __syncthreads();

    // Phase B: log-diff partials (float per-thread, 8 terms each)
    const int N = S - 2;
    float fs = 0.f, fss = 0.f;
    for (int i = tid; i < N; i += nthr) {
        float d = fabsf(t_sh[i + 2] - t_sh[i]);
        float l = logf(d + 1e-6f);
        fs  += l;
        fss = fmaf(l, l, fss);
    }
    double s = (double)fs, ss = (double)fss;
    #pragma unroll
    for (int off = 16; off; off >>= 1) {
        s  += __shfl_xor_sync(0xffffffffu, s,  off);
        ss += __shfl_xor_sync(0xffffffffu, ss, off);
    }
    if (lane == 0) { sh_s[wid] = s; sh_ss[wid] = ss; }
    __syncthreads();
    if (wid == 0) {
        double ts  = (lane < 16) ? sh_s[lane]  : 0.0;
        double tss = (lane < 16) ? sh_ss[lane] : 0.0;
        #pragma unroll
        for (int off = 8; off; off >>= 1) {
            ts  += __shfl_xor_sync(0xffffffffu, ts,  off);
            tss += __shfl_xor_sync(0xffffffffu, tss, off);
        }
        if (lane == 0) {
            const double Nd = (double)N;
            double mean = ts / Nd;
            double var  = (tss - ts * ts / Nd) / (Nd - 1.0);
            if (var < 0.0) var = 0.0;
            sh_stats[0] = (float)mean;
            sh_stats[1] = (float)sqrt(var);
        }
    }
    __syncthreads();

    if (tid < dout)
        sh_o[tid] = tanhf(sh_stats[0] * w3[2*tid] + sh_stats[1] * w3[2*tid + 1] + b3[tid]);
    __syncthreads();

    float4* __restrict__ ob = reinterpret_cast<float4*>(out + (size_t)b * dout * dout);
    const float4* __restrict__ so = reinterpret_cast<const float4*>(sh_o);
    const int total4 = (dout * dout) >> 2;   // 1024
    const int row4   = dout >> 2;            // 16
    for (int k = tid; k < total4; k += nthr)
        ob[k] = so[k & (row4 - 1)];
}

extern "C" void kernel_launch(void* const* d_in, const int* in_sizes, int n_in,
                              void* d_out, int out_size)
{
    const float* x  = (const float*)d_in[0];
    const float* w1 = (const float*)d_in[1];
    const float* b1 = (const float*)d_in[2];
    const float* w2 = (const float*)d_in[3];
    const float* b2 = (const float*)d_in[4];
    const float* w3 = (const float*)d_in[5];
    const float* b3 = (const float*)d_in[6];
    float* out = (float*)d_out;

    const int DOUT = 64;
    const int B    = out_size / (DOUT * DOUT);   // 128
    const int rows = in_sizes[0] / 128;          // B * S
    const int S    = rows / B;                   // 4096

    // Kernel 1: normal launch (296 blocks, 2 CTA/SM, all 148 SMs).
    {
        cudaLaunchConfig_t cfg = {};
        cfg.gridDim  = dim3(296);
        cfg.blockDim = dim3(256);
        cfg.stream   = 0;
        void* args[] = { (void*)&x, (void*)&w1, (void*)&b1, (void*)&w2, (void*)&b2,
                         (void*)&rows };
        int r = rows;
        void* args2[] = { (void*)&x, (void*)&w1, (void*)&b1, (void*)&w2, (void*)&b2,
                          (void*)&r };
        (void)args;
        cudaLaunchKernelExC(&cfg, (const void*)k_transform, args2);
    }

    // Kernel 2: PDL launch — overlaps its ramp with k_transform's tail.
    {
        cudaLaunchAttribute attr[1];
        attr[0].id = cudaLaunchAttributeProgrammaticStreamSerialization;
        attr[0].val.programmaticStreamSerializationAllowed = 1;

        cudaLaunchConfig_t cfg = {};
        cfg.gridDim  = dim3(B);
        cfg.blockDim = dim3(512);
        cfg.stream   = 0;
        cfg.attrs    = attr;
        cfg.numAttrs = 1;

        int s_ = S, d_ = DOUT;
        void* args[] = { (void*)&w3, (void*)&b3, (void*)&out, (void*)&s_, (void*)&d_ };
        cudaLaunchKernelExC(&cfg, (const void*)k_stats, args);
    }
}